// round 17
// baseline (speedup 1.0000x reference)
#include <cuda_runtime.h>

// Problem constants
#define B_SZ 4096
#define T_SZ 200
#define D_SZ 64
#define P_SZ 2
#define TM1 (T_SZ - 1)     // 199
#define COV_ROW (D_SZ + 1) // 65

// One wave at 5 blocks/SM: 148 x 5 (51-reg budget for the 8-row unroll)
#define BLOCKS_PER_SM 5
#define GRID_N (148 * BLOCKS_PER_SM)   // 740
#define BLOCK_N 256
#define NWARP (BLOCK_N / 32)           // 8 warps

// Global accumulators + work queue. Static-init to 0; the finalizing block
// resets everything for the next graph replay.
__device__ double g_acc[3] = {0.0, 0.0, 0.0};
__device__ unsigned int g_ticket = 0;
__device__ unsigned int g_batch_ctr = 0;

// Reduce one float across the block; result valid on thread 0.
__device__ __forceinline__ float block_reduce(float v, float* shmem) {
    #pragma unroll
    for (int off = 16; off > 0; off >>= 1)
        v += __shfl_down_sync(0xFFFFFFFFu, v, off);
    int lane = threadIdx.x & 31;
    int wid  = threadIdx.x >> 5;
    if (lane == 0) shmem[wid] = v;
    __syncthreads();
    if (wid == 0) {
        float s = (lane < NWARP) ? shmem[lane] : 0.0f;
        #pragma unroll
        for (int off = 16; off > 0; off >>= 1)
            s += __shfl_down_sync(0xFFFFFFFFu, s, off);
        return s;
    }
    return 0.0f;
}

__global__ void __launch_bounds__(BLOCK_N, BLOCKS_PER_SM)
main_kernel(const float* __restrict__ pred_params,
            const float* __restrict__ step_preds,
            const float* __restrict__ cov,
            const float* __restrict__ theta,
            const int*   __restrict__ lengths,
            float*       __restrict__ out) {
    __shared__ float shmem[32];
    __shared__ int cur_b;

    float block_step, block_drift, block_gdiff;

    // ---- Phase 1: step-ahead term; warp-per-row, 8 rows in flight ----
    // Quantum = one batch. Warp w covers rows t = w, w+8, ...; the 8-row
    // unroll keeps 24 loads (~4KB) outstanding per warp.
    // Lane owns elements d = 2*lane, 2*lane+1 (aligned float2 pred + 2 scalar cov).
    {
        const int w    = threadIdx.x >> 5;
        const int lane = threadIdx.x & 31;

        float local = 0.0f;
        for (;;) {
            if (threadIdx.x == 0)
                cur_b = (int)atomicAdd(&g_batch_ctr, 1u);
            __syncthreads();
            const int b = cur_b;
            __syncthreads();   // protect cur_b before next pop overwrites it
            if (b >= B_SZ) break;

            const int nrow = lengths[b] - 1;      // live rows: t in [0, nrow)
            if (nrow <= 0) continue;

            const float* __restrict__ p0 =
                step_preds + (size_t)b * TM1 * D_SZ + (size_t)w * D_SZ + (lane << 1);
            const float* __restrict__ c0 =
                cov + (size_t)b * T_SZ * COV_ROW + (size_t)(w + 1) * COV_ROW + 1 + (lane << 1);

            // Strides for one warp-row step (8 rows of the batch)
            const int PSTEP = 8 * D_SZ;       // 512 floats
            const int CSTEP = 8 * COV_ROW;    // 520 floats

            float bacc = 0.0f;
            int t = w;
            // 8 rows in flight: t, t+8, ..., t+56
            for (; t + 56 < nrow; t += 64) {
                float2 pr[8];
                float  cv[16];
                #pragma unroll
                for (int k = 0; k < 8; k++) {
                    pr[k] = __ldcs(reinterpret_cast<const float2*>(p0 + k * PSTEP));
                }
                #pragma unroll
                for (int k = 0; k < 8; k++) {
                    cv[2*k + 0] = __ldcs(c0 + k * CSTEP + 0);
                    cv[2*k + 1] = __ldcs(c0 + k * CSTEP + 1);
                }
                #pragma unroll
                for (int k = 0; k < 8; k++) {
                    float d0 = cv[2*k + 0] - pr[k].x;
                    float d1 = cv[2*k + 1] - pr[k].y;
                    bacc += d0 * d0 + d1 * d1;
                }
                p0 += 8 * PSTEP;
                c0 += 8 * CSTEP;
            }
            // Remainder: up to 7 more rows for this warp
            for (; t < nrow; t += 8) {
                const float2 pa = __ldcs(reinterpret_cast<const float2*>(p0));
                float d0 = __ldcs(c0 + 0) - pa.x;
                float d1 = __ldcs(c0 + 1) - pa.y;
                bacc += d0 * d0 + d1 * d1;
                p0 += PSTEP;
                c0 += CSTEP;
            }
            local += bacc * (1.0f / ((float)nrow * (float)D_SZ));
        }

        block_step = block_reduce(local, shmem);
        __syncthreads();  // shmem reuse
    }

    // ---- Phase 2: drift + global-diff over pred_params [B,T,2] ----
    {
        const float inv_th0 = 1.0f / theta[0];
        const float inv_th1 = 1.0f / theta[1];
        const int n = B_SZ * T_SZ;   // 819200 float2 elements
        const int stride = GRID_N * BLOCK_N;

        float drift = 0.0f;
        float gdiff = 0.0f;
        for (int i = blockIdx.x * BLOCK_N + threadIdx.x; i < n; i += stride) {
            int t = i % T_SZ;
            float2 x = reinterpret_cast<const float2*>(pred_params)[i];
            float e0 = x.x * inv_th0 - 1.0f;
            float e1 = x.y * inv_th1 - 1.0f;
            gdiff += e0 * e0 + e1 * e1;
            if (t < T_SZ - 1) {
                float2 y = reinterpret_cast<const float2*>(pred_params)[i + 1];
                float d0 = x.x - y.x;
                float d1 = x.y - y.y;
                drift += d0 * d0 + d1 * d1;
            }
        }
        block_drift = block_reduce(drift, shmem);
        __syncthreads();
        block_gdiff = block_reduce(gdiff, shmem);
    }

    // ---- Phase 3: thread-0-only commit + ticket; last block finalizes ----
    __shared__ bool is_last;
    if (threadIdx.x == 0) {
        atomicAdd(&g_acc[0], (double)block_step);
        atomicAdd(&g_acc[1], (double)block_drift);
        atomicAdd(&g_acc[2], (double)block_gdiff);
        __threadfence();
        unsigned int t = atomicInc(&g_ticket, GRID_N - 1);  // wraps to 0
        is_last = (t == GRID_N - 1);
    }
    __syncthreads();
    if (!is_last) return;

    if (threadIdx.x == 0) {
        __threadfence();
        double step  = g_acc[0] / (double)B_SZ;
        double drift = g_acc[1] / ((double)B_SZ * (double)TM1 * (double)P_SZ);
        double gdiff = g_acc[2] / ((double)B_SZ * (double)T_SZ * (double)P_SZ);
        out[0] = (float)(step + 0.1 * drift + 0.01 * gdiff);
        // Reset state for the next graph replay.
        g_acc[0] = 0.0; g_acc[1] = 0.0; g_acc[2] = 0.0;
        g_batch_ctr = 0;
        __threadfence();
    }
}

extern "C" void kernel_launch(void* const* d_in, const int* in_sizes, int n_in,
                              void* d_out, int out_size) {
    const float* global_theta = (const float*)d_in[0];
    const float* pred_params  = (const float*)d_in[1];
    // d_in[2] = hidden_states: UNUSED by the reference
    const float* step_preds   = (const float*)d_in[3];
    const float* cov_trajs    = (const float*)d_in[4];
    const int*   lengths      = (const int*)d_in[5];
    float* out = (float*)d_out;

    main_kernel<<<GRID_N, BLOCK_N>>>(pred_params, step_preds, cov_trajs,
                                     global_theta, lengths, out);
}